// round 15
// baseline (speedup 1.0000x reference)
#include <cuda_runtime.h>
#include <cstdint>
#include <math.h>

#define BB 8
#define LC 512
#define LQ 64
#define DD 256
#define TI 32
#define NT 256
#define SA 260                  // hi/lo tile row stride (words): conflict-free frag loads
#define SS 68                   // S tile row stride
#define NEG_BIG 1e30f

// dynamic smem layout (float offsets)
#define OFF_CH 0                          // ctx hi  [32][SA]
#define OFF_CL (OFF_CH + TI * SA)         // ctx lo
#define OFF_QH (OFF_CL + TI * SA)         // (wp*q) hi [64][SA]
#define OFF_QL (OFF_QH + LQ * SA)         // (wp*q) lo
#define OFF_S  (OFF_QL + LQ * SA)         // S [32][SS]
#define DYN_FLOATS (OFF_S + TI * SS)
#define DYN_BYTES  (DYN_FLOATS * 4)       // ~208 KB

__device__ float g_part[BB * 16 * 4];     // (mloc, ploc, uloc, pad) per block
__device__ unsigned int g_cnt[BB];
__device__ unsigned int g_cnt2[BB];

__device__ __forceinline__ float tf32r(float x) {
    float r;
    asm("cvt.rna.tf32.f32 %0, %1;" : "=f"(r) : "f"(x));
    return r;
}
__device__ __forceinline__ void mma8(float* d, const uint32_t* a, const uint32_t* bb) {
    asm volatile(
        "mma.sync.aligned.m16n8k8.row.col.f32.tf32.tf32.f32 "
        "{%0,%1,%2,%3}, {%4,%5,%6,%7}, {%8,%9}, {%0,%1,%2,%3};"
        : "+f"(d[0]), "+f"(d[1]), "+f"(d[2]), "+f"(d[3])
        : "r"(a[0]), "r"(a[1]), "r"(a[2]), "r"(a[3]), "r"(bb[0]), "r"(bb[1]));
}

__global__ __launch_bounds__(NT, 1) void bi_attn_fused(
    const float* __restrict__ ctx, const float* __restrict__ qst,
    const int* __restrict__ mask, const float* __restrict__ att_w,
    const float* __restrict__ att_b, const float* __restrict__ w_in,
    const float* __restrict__ w_mem, float* __restrict__ out)
{
    extern __shared__ __align__(128) float dsm[];
    __shared__ float s_sc[TI], s_c1[TI], s_sq[LQ], s_q1[LQ];
    __shared__ float s_m[TI], s_u[TI];
    __shared__ float s_red[4];

    const int b   = blockIdx.y;
    const int i0  = blockIdx.x * TI;
    const int tid = threadIdx.x;

    const float4* ctx4 = (const float4*)(ctx + ((size_t)b * LC + i0) * DD);
    const float4* q4   = (const float4*)(qst + (size_t)b * LQ * DD);
    const float4* wc4  = (const float4*)att_w;          // [0,64)
    const float4* wq4  = wc4 + 64;                      // att_w[256..512)
    const float4* wp4  = wc4 + 128;                     // att_w[512..768)
    const float4* wi4  = (const float4*)w_in;
    const float4* wm4  = (const float4*)w_mem;

    const int cr  = tid >> 3, cf  = tid & 7;   // ctx: 32 rows x 8 thr (f = cf + 8k)
    const int qr  = tid >> 2, qf0 = tid & 3;   // q:   64 rows x 4 thr (f = qf0 + 4k)
    const int ti_ = tid >> 4, tj_ = tid & 15;

    // ---- MAXIMUM MLP: all 24 data LDG.128 issued before any consumption ----
    float4 cv[8];
#pragma unroll
    for (int k = 0; k < 8; k++) cv[k] = __ldg(&ctx4[(size_t)cr * 64 + cf + 8 * k]);
    float4 qv[16];
#pragma unroll
    for (int k = 0; k < 16; k++) qv[k] = __ldg(&q4[(size_t)qr * 64 + qf0 + 4 * k]);

    // tiny operands
    const float bias = __ldg(att_b);
    const int4 mv = __ldg(&((const int4*)(mask + b * LQ))[tj_]);

    // ---- ctx staging: dots (weights via __ldg, L2-broadcast) + tf32 split ----
    float sc_p = 0.f, c1_p = 0.f;
#pragma unroll
    for (int k = 0; k < 8; k++) {
        const int f  = cf + 8 * k;
        const int dg = f * 4;
        float4 v   = cv[k];
        float4 wcv = __ldg(&wc4[f]);
        float4 wiv = __ldg(&wi4[f]);
        sc_p += v.x * wcv.x + v.y * wcv.y + v.z * wcv.z + v.w * wcv.w;
        c1_p += v.x * wiv.x + v.y * wiv.y + v.z * wiv.z + v.w * wiv.w;
        float4 h, l;
        h.x = tf32r(v.x); l.x = tf32r(v.x - h.x);
        h.y = tf32r(v.y); l.y = tf32r(v.y - h.y);
        h.z = tf32r(v.z); l.z = tf32r(v.z - h.z);
        h.w = tf32r(v.w); l.w = tf32r(v.w - h.w);
        *(float4*)&dsm[OFF_CH + cr * SA + dg] = h;
        *(float4*)&dsm[OFF_CL + cr * SA + dg] = l;
    }
    sc_p += __shfl_xor_sync(0xffffffffu, sc_p, 1);
    sc_p += __shfl_xor_sync(0xffffffffu, sc_p, 2);
    sc_p += __shfl_xor_sync(0xffffffffu, sc_p, 4);
    c1_p += __shfl_xor_sync(0xffffffffu, c1_p, 1);
    c1_p += __shfl_xor_sync(0xffffffffu, c1_p, 2);
    c1_p += __shfl_xor_sync(0xffffffffu, c1_p, 4);
    if (cf == 0) { s_sc[cr] = sc_p; s_c1[cr] = c1_p; }

    // ---- q staging: dots, wp-premul, tf32 split ----
    float sq_p = 0.f, q1_p = 0.f;
#pragma unroll
    for (int k = 0; k < 16; k++) {
        const int f  = qf0 + 4 * k;
        const int dg = f * 4;
        float4 v   = qv[k];
        float4 wqv = __ldg(&wq4[f]);
        float4 wmv = __ldg(&wm4[f]);
        float4 wpv = __ldg(&wp4[f]);
        sq_p += v.x * wqv.x + v.y * wqv.y + v.z * wqv.z + v.w * wqv.w;
        q1_p += v.x * wmv.x + v.y * wmv.y + v.z * wmv.z + v.w * wmv.w;
        float4 y = make_float4(v.x * wpv.x, v.y * wpv.y, v.z * wpv.z, v.w * wpv.w);
        float4 h, l;
        h.x = tf32r(y.x); l.x = tf32r(y.x - h.x);
        h.y = tf32r(y.y); l.y = tf32r(y.y - h.y);
        h.z = tf32r(y.z); l.z = tf32r(y.z - h.z);
        h.w = tf32r(y.w); l.w = tf32r(y.w - h.w);
        *(float4*)&dsm[OFF_QH + qr * SA + dg] = h;
        *(float4*)&dsm[OFF_QL + qr * SA + dg] = l;
    }
    sq_p += __shfl_xor_sync(0xffffffffu, sq_p, 1);
    sq_p += __shfl_xor_sync(0xffffffffu, sq_p, 2);
    q1_p += __shfl_xor_sync(0xffffffffu, q1_p, 1);
    q1_p += __shfl_xor_sync(0xffffffffu, q1_p, 2);
    if (qf0 == 0) { s_sq[qr] = sq_p; s_q1[qr] = q1_p; }
    __syncthreads();   // single pre-GEMM barrier

    // ---- tensor-core GEMM (unchanged) ----
    {
        const int warp = tid >> 5, lid = tid & 31;
        const int g = lid >> 2, t = lid & 3;
        const int m  = (warp >> 2) * 16;
        const int n0 = (warp & 3) * 16;
        const uint32_t* Ch = (const uint32_t*)&dsm[OFF_CH];
        const uint32_t* Cl = (const uint32_t*)&dsm[OFF_CL];
        const uint32_t* Qh = (const uint32_t*)&dsm[OFF_QH];
        const uint32_t* Ql = (const uint32_t*)&dsm[OFF_QL];
        const int ra = (m + g) * SA, rb = (m + g + 8) * SA;
        const int nb0 = (n0 + g) * SA, nb1 = (n0 + 8 + g) * SA;

        float d0[2][4] = {}, d1[2][4] = {};
#pragma unroll 4
        for (int k0 = 0; k0 < DD; k0 += 8) {
            uint32_t ah[4], al[4], bh[2][2], bl[2][2];
            ah[0] = Ch[ra + k0 + t];     ah[1] = Ch[rb + k0 + t];
            ah[2] = Ch[ra + k0 + t + 4]; ah[3] = Ch[rb + k0 + t + 4];
            al[0] = Cl[ra + k0 + t];     al[1] = Cl[rb + k0 + t];
            al[2] = Cl[ra + k0 + t + 4]; al[3] = Cl[rb + k0 + t + 4];
            bh[0][0] = Qh[nb0 + k0 + t]; bh[0][1] = Qh[nb0 + k0 + t + 4];
            bh[1][0] = Qh[nb1 + k0 + t]; bh[1][1] = Qh[nb1 + k0 + t + 4];
            bl[0][0] = Ql[nb0 + k0 + t]; bl[0][1] = Ql[nb0 + k0 + t + 4];
            bl[1][0] = Ql[nb1 + k0 + t]; bl[1][1] = Ql[nb1 + k0 + t + 4];
#pragma unroll
            for (int s = 0; s < 2; s++) {
                mma8(d0[s], ah, bh[s]);
                mma8(d1[s], ah, bl[s]);
                mma8(d1[s], al, bh[s]);
            }
        }
#pragma unroll
        for (int s = 0; s < 2; s++) {
            const int nc = n0 + 8 * s + 2 * t;
            *(float2*)&dsm[OFF_S + (m + g) * SS + nc] =
                make_float2(d0[s][0] + d1[s][0], d0[s][1] + d1[s][1]);
            *(float2*)&dsm[OFF_S + (m + g + 8) * SS + nc] =
                make_float2(d0[s][2] + d1[s][2], d0[s][3] + d1[s][3]);
        }
    }
    __syncthreads();   // S visible

    // ---- per-row softmax -> s_m / s_u ----
    float myq1[4], addj[4];
    {
        float pen0 = -NEG_BIG * (1.0f - (float)mv.x);
        float pen1 = -NEG_BIG * (1.0f - (float)mv.y);
        float pen2 = -NEG_BIG * (1.0f - (float)mv.z);
        float pen3 = -NEG_BIG * (1.0f - (float)mv.w);
        int j = tj_ * 4;
        myq1[0] = s_q1[j];     addj[0] = s_sq[j]     + pen0 + bias;
        myq1[1] = s_q1[j + 1]; addj[1] = s_sq[j + 1] + pen1 + bias;
        myq1[2] = s_q1[j + 2]; addj[2] = s_sq[j + 2] + pen2 + bias;
        myq1[3] = s_q1[j + 3]; addj[3] = s_sq[j + 3] + pen3 + bias;
    }
#pragma unroll
    for (int a = 0; a < 2; a++) {
        int i = ti_ * 2 + a;
        float sci = s_sc[i];
        float4 sv = *(const float4*)&dsm[OFF_S + i * SS + tj_ * 4];
        float l[4], mx = -INFINITY;
        l[0] = sv.x + sci + addj[0];
        l[1] = sv.y + sci + addj[1];
        l[2] = sv.z + sci + addj[2];
        l[3] = sv.w + sci + addj[3];
#pragma unroll
        for (int e = 0; e < 4; e++) mx = fmaxf(mx, l[e]);
#pragma unroll
        for (int s = 1; s < 16; s <<= 1)
            mx = fmaxf(mx, __shfl_xor_sync(0xffffffffu, mx, s));
        float num = 0.f, den = 0.f;
#pragma unroll
        for (int e = 0; e < 4; e++) {
            float ev = __expf(l[e] - mx);
            num += ev * myq1[e];
            den += ev;
        }
#pragma unroll
        for (int s = 1; s < 16; s <<= 1) {
            num += __shfl_xor_sync(0xffffffffu, num, s);
            den += __shfl_xor_sync(0xffffffffu, den, s);
        }
        if (tj_ == 0) { s_m[i] = mx; s_u[i] = num / den; }
    }
    __syncthreads();   // s_m/s_u/s_c1 ready

    // ---- publish block partial, spin for all 16 partials of this batch ----
    if (tid < 32) {
        float m_i = s_m[tid], c1_i = s_c1[tid];
        float mloc = m_i;
#pragma unroll
        for (int s = 16; s > 0; s >>= 1)
            mloc = fmaxf(mloc, __shfl_xor_sync(0xffffffffu, mloc, s));
        float e = __expf(m_i - mloc);
        float p = e, u = e * c1_i;
#pragma unroll
        for (int s = 16; s > 0; s >>= 1) {
            p += __shfl_xor_sync(0xffffffffu, p, s);
            u += __shfl_xor_sync(0xffffffffu, u, s);
        }
        if (tid == 0) {
            *(float4*)&g_part[(b * 16 + blockIdx.x) * 4] = make_float4(mloc, p, u, 0.f);
            __threadfence();                 // release partial
            atomicAdd(&g_cnt[b], 1u);
            unsigned v;
            do {
                asm volatile("ld.global.acquire.gpu.u32 %0, [%1];"
                             : "=r"(v) : "l"(&g_cnt[b]) : "memory");
            } while (v < 16u);
        }
    }
    __syncthreads();   // everyone past the batch barrier
    __threadfence();   // order partial reads after acquire

    // ---- every block computes H from the 16 triples ----
    if (tid < 16) {
        float4 tp = __ldcg((const float4*)&g_part[(b * 16 + tid) * 4]);
        float M = tp.x;
#pragma unroll
        for (int s = 8; s > 0; s >>= 1)
            M = fmaxf(M, __shfl_xor_sync(0x0000ffffu, M, s));
        float scl = __expf(tp.x - M);
        float den = tp.y * scl, num = tp.z * scl;
#pragma unroll
        for (int s = 8; s > 0; s >>= 1) {
            den += __shfl_xor_sync(0x0000ffffu, den, s);
            num += __shfl_xor_sync(0x0000ffffu, num, s);
        }
        if (tid == 0) s_red[0] = num / den;
    }
    __syncthreads();
    const float H = s_red[0];

    // ---- one coalesced 512B output burst for this block's 32 rows ----
    if (tid < 32) {
        float U = s_u[tid], c1 = s_c1[tid];
        ((float4*)out)[(size_t)b * LC + i0 + tid] = make_float4(c1, U, c1 * U, U * H);
    }

    // ---- replay-safe counter reset ----
    if (tid == 0) {
        unsigned old = atomicAdd(&g_cnt2[b], 1u);
        if (old == 15u) { g_cnt[b] = 0; g_cnt2[b] = 0; }
    }
}

extern "C" void kernel_launch(void* const* d_in, const int* in_sizes, int n_in,
                              void* d_out, int out_size)
{
    const float* ctx   = (const float*)d_in[0];  // (8,512,256)
    const float* qst   = (const float*)d_in[1];  // (8,64,256)
    const int*   mask  = (const int*)d_in[2];    // (8,64)
    const float* att_w = (const float*)d_in[3];  // (768,)
    const float* att_b = (const float*)d_in[4];  // (1,)
    const float* w_in  = (const float*)d_in[5];  // (256,)
    const float* w_mem = (const float*)d_in[6];  // (256,)
    float* out = (float*)d_out;                  // (8,512,4)

    cudaFuncSetAttribute(bi_attn_fused,
                         cudaFuncAttributeMaxDynamicSharedMemorySize, DYN_BYTES);
    dim3 grid(LC / TI, BB);
    bi_attn_fused<<<grid, NT, DYN_BYTES>>>(ctx, qst, mask, att_w, att_b,
                                           w_in, w_mem, out);
}

// round 16
// speedup vs baseline: 1.6400x; 1.6400x over previous
#include <cuda_runtime.h>
#include <cstdint>
#include <math.h>

#define BB 8
#define LC 512
#define LQ 64
#define DD 256
#define TI 32
#define NT 256
#define SA 260                  // hi/lo tile row stride (words): conflict-free frag loads
#define SS 68                   // S tile row stride
#define NEG_BIG 1e30f

// dynamic smem layout (float offsets)
#define OFF_CH 0                          // ctx hi  [32][SA]
#define OFF_CL (OFF_CH + TI * SA)         // ctx lo
#define OFF_QH (OFF_CL + TI * SA)         // (wp*q) hi [64][SA]
#define OFF_QL (OFF_QH + LQ * SA)         // (wp*q) lo
#define OFF_S  (OFF_QL + LQ * SA)         // S [32][SS]
#define DYN_FLOATS (OFF_S + TI * SS)
#define DYN_BYTES  (DYN_FLOATS * 4)       // ~208 KB

__device__ float g_part[BB * 16 * 4];     // (mloc, ploc, uloc, pad) per block
__device__ unsigned int g_cnt[BB];
__device__ unsigned int g_cnt2[BB];

__device__ __forceinline__ float tf32r(float x) {
    float r;
    asm("cvt.rna.tf32.f32 %0, %1;" : "=f"(r) : "f"(x));
    return r;
}
__device__ __forceinline__ void mma8(float* d, const uint32_t* a, const uint32_t* bb) {
    asm volatile(
        "mma.sync.aligned.m16n8k8.row.col.f32.tf32.tf32.f32 "
        "{%0,%1,%2,%3}, {%4,%5,%6,%7}, {%8,%9}, {%0,%1,%2,%3};"
        : "+f"(d[0]), "+f"(d[1]), "+f"(d[2]), "+f"(d[3])
        : "r"(a[0]), "r"(a[1]), "r"(a[2]), "r"(a[3]), "r"(bb[0]), "r"(bb[1]));
}

__global__ __launch_bounds__(NT, 1) void bi_attn_fused(
    const float* __restrict__ ctx, const float* __restrict__ qst,
    const int* __restrict__ mask, const float* __restrict__ att_w,
    const float* __restrict__ att_b, const float* __restrict__ w_in,
    const float* __restrict__ w_mem, float* __restrict__ out)
{
    extern __shared__ __align__(128) float dsm[];
    __shared__ float s_sc[TI], s_c1[TI], s_sq[LQ], s_q1[LQ];
    __shared__ float s_m[TI], s_u[TI];

    const int b   = blockIdx.y;
    const int i0  = blockIdx.x * TI;
    const int tid = threadIdx.x;

    const float4* ctx4 = (const float4*)(ctx + ((size_t)b * LC + i0) * DD);
    const float4* q4   = (const float4*)(qst + (size_t)b * LQ * DD);
    const float4* wc4  = (const float4*)att_w;          // [0,64)
    const float4* wq4  = wc4 + 64;                      // att_w[256..512)
    const float4* wp4  = wc4 + 128;                     // att_w[512..768)
    const float4* wi4  = (const float4*)w_in;
    const float4* wm4  = (const float4*)w_mem;

    const int cr  = tid >> 3, cf  = tid & 7;   // ctx: 32 rows x 8 thr (f = cf + 8k)
    const int qr  = tid >> 2, qf0 = tid & 3;   // q:   64 rows x 4 thr (f = qf0 + 4k)
    const int ti_ = tid >> 4, tj_ = tid & 15;

    // tiny operands early
    const float bias = __ldg(att_b);
    const int4 mv = __ldg(&((const int4*)(mask + b * LQ))[tj_]);

    // ---- double-buffered staging: groups of 4 float4 in flight (R14-proven) ----
    float4 cbuf[2][4], qbuf[2][4];
#pragma unroll
    for (int k = 0; k < 4; k++) cbuf[0][k] = __ldg(&ctx4[(size_t)cr * 64 + cf + 8 * k]);
#pragma unroll
    for (int k = 0; k < 4; k++) qbuf[0][k] = __ldg(&q4[(size_t)qr * 64 + qf0 + 4 * k]);

    float sc_p = 0.f, c1_p = 0.f;
#pragma unroll
    for (int g = 0; g < 2; g++) {
        if (g < 1)
#pragma unroll
            for (int k = 0; k < 4; k++)
                cbuf[1][k] = __ldg(&ctx4[(size_t)cr * 64 + cf + 8 * (4 + k)]);
#pragma unroll
        for (int k = 0; k < 4; k++) {
            const int f  = cf + 8 * (4 * g + k);
            const int dg = f * 4;
            float4 v   = cbuf[g & 1][k];
            float4 wcv = __ldg(&wc4[f]);
            float4 wiv = __ldg(&wi4[f]);
            sc_p += v.x * wcv.x + v.y * wcv.y + v.z * wcv.z + v.w * wcv.w;
            c1_p += v.x * wiv.x + v.y * wiv.y + v.z * wiv.z + v.w * wiv.w;
            float4 h, l;
            h.x = tf32r(v.x); l.x = tf32r(v.x - h.x);
            h.y = tf32r(v.y); l.y = tf32r(v.y - h.y);
            h.z = tf32r(v.z); l.z = tf32r(v.z - h.z);
            h.w = tf32r(v.w); l.w = tf32r(v.w - h.w);
            *(float4*)&dsm[OFF_CH + cr * SA + dg] = h;
            *(float4*)&dsm[OFF_CL + cr * SA + dg] = l;
        }
    }
    sc_p += __shfl_xor_sync(0xffffffffu, sc_p, 1);
    sc_p += __shfl_xor_sync(0xffffffffu, sc_p, 2);
    sc_p += __shfl_xor_sync(0xffffffffu, sc_p, 4);
    c1_p += __shfl_xor_sync(0xffffffffu, c1_p, 1);
    c1_p += __shfl_xor_sync(0xffffffffu, c1_p, 2);
    c1_p += __shfl_xor_sync(0xffffffffu, c1_p, 4);
    if (cf == 0) { s_sc[cr] = sc_p; s_c1[cr] = c1_p; }

    float sq_p = 0.f, q1_p = 0.f;
#pragma unroll
    for (int g = 0; g < 4; g++) {
        if (g < 3)
#pragma unroll
            for (int k = 0; k < 4; k++)
                qbuf[(g + 1) & 1][k] =
                    __ldg(&q4[(size_t)qr * 64 + qf0 + 4 * (4 * (g + 1) + k)]);
#pragma unroll
        for (int k = 0; k < 4; k++) {
            const int f  = qf0 + 4 * (4 * g + k);
            const int dg = f * 4;
            float4 v   = qbuf[g & 1][k];
            float4 wqv = __ldg(&wq4[f]);
            float4 wmv = __ldg(&wm4[f]);
            float4 wpv = __ldg(&wp4[f]);
            sq_p += v.x * wqv.x + v.y * wqv.y + v.z * wqv.z + v.w * wqv.w;
            q1_p += v.x * wmv.x + v.y * wmv.y + v.z * wmv.z + v.w * wmv.w;
            float4 y = make_float4(v.x * wpv.x, v.y * wpv.y, v.z * wpv.z, v.w * wpv.w);
            float4 h, l;
            h.x = tf32r(y.x); l.x = tf32r(y.x - h.x);
            h.y = tf32r(y.y); l.y = tf32r(y.y - h.y);
            h.z = tf32r(y.z); l.z = tf32r(y.z - h.z);
            h.w = tf32r(y.w); l.w = tf32r(y.w - h.w);
            *(float4*)&dsm[OFF_QH + qr * SA + dg] = h;
            *(float4*)&dsm[OFF_QL + qr * SA + dg] = l;
        }
    }
    sq_p += __shfl_xor_sync(0xffffffffu, sq_p, 1);
    sq_p += __shfl_xor_sync(0xffffffffu, sq_p, 2);
    q1_p += __shfl_xor_sync(0xffffffffu, q1_p, 1);
    q1_p += __shfl_xor_sync(0xffffffffu, q1_p, 2);
    if (qf0 == 0) { s_sq[qr] = sq_p; s_q1[qr] = q1_p; }
    __syncthreads();   // single pre-GEMM barrier

    // ---- tensor-core GEMM (unchanged) ----
    {
        const int warp = tid >> 5, lid = tid & 31;
        const int g = lid >> 2, t = lid & 3;
        const int m  = (warp >> 2) * 16;
        const int n0 = (warp & 3) * 16;
        const uint32_t* Ch = (const uint32_t*)&dsm[OFF_CH];
        const uint32_t* Cl = (const uint32_t*)&dsm[OFF_CL];
        const uint32_t* Qh = (const uint32_t*)&dsm[OFF_QH];
        const uint32_t* Ql = (const uint32_t*)&dsm[OFF_QL];
        const int ra = (m + g) * SA, rb = (m + g + 8) * SA;
        const int nb0 = (n0 + g) * SA, nb1 = (n0 + 8 + g) * SA;

        float d0[2][4] = {}, d1[2][4] = {};
#pragma unroll 4
        for (int k0 = 0; k0 < DD; k0 += 8) {
            uint32_t ah[4], al[4], bh[2][2], bl[2][2];
            ah[0] = Ch[ra + k0 + t];     ah[1] = Ch[rb + k0 + t];
            ah[2] = Ch[ra + k0 + t + 4]; ah[3] = Ch[rb + k0 + t + 4];
            al[0] = Cl[ra + k0 + t];     al[1] = Cl[rb + k0 + t];
            al[2] = Cl[ra + k0 + t + 4]; al[3] = Cl[rb + k0 + t + 4];
            bh[0][0] = Qh[nb0 + k0 + t]; bh[0][1] = Qh[nb0 + k0 + t + 4];
            bh[1][0] = Qh[nb1 + k0 + t]; bh[1][1] = Qh[nb1 + k0 + t + 4];
            bl[0][0] = Ql[nb0 + k0 + t]; bl[0][1] = Ql[nb0 + k0 + t + 4];
            bl[1][0] = Ql[nb1 + k0 + t]; bl[1][1] = Ql[nb1 + k0 + t + 4];
#pragma unroll
            for (int s = 0; s < 2; s++) {
                mma8(d0[s], ah, bh[s]);
                mma8(d1[s], ah, bl[s]);
                mma8(d1[s], al, bh[s]);
            }
        }
#pragma unroll
        for (int s = 0; s < 2; s++) {
            const int nc = n0 + 8 * s + 2 * t;
            *(float2*)&dsm[OFF_S + (m + g) * SS + nc] =
                make_float2(d0[s][0] + d1[s][0], d0[s][1] + d1[s][1]);
            *(float2*)&dsm[OFF_S + (m + g + 8) * SS + nc] =
                make_float2(d0[s][2] + d1[s][2], d0[s][3] + d1[s][3]);
        }
    }
    __syncthreads();   // S visible

    // ---- per-row softmax -> s_m / s_u ----
    float myq1[4], addj[4];
    {
        float pen0 = -NEG_BIG * (1.0f - (float)mv.x);
        float pen1 = -NEG_BIG * (1.0f - (float)mv.y);
        float pen2 = -NEG_BIG * (1.0f - (float)mv.z);
        float pen3 = -NEG_BIG * (1.0f - (float)mv.w);
        int j = tj_ * 4;
        myq1[0] = s_q1[j];     addj[0] = s_sq[j]     + pen0 + bias;
        myq1[1] = s_q1[j + 1]; addj[1] = s_sq[j + 1] + pen1 + bias;
        myq1[2] = s_q1[j + 2]; addj[2] = s_sq[j + 2] + pen2 + bias;
        myq1[3] = s_q1[j + 3]; addj[3] = s_sq[j + 3] + pen3 + bias;
    }
#pragma unroll
    for (int a = 0; a < 2; a++) {
        int i = ti_ * 2 + a;
        float sci = s_sc[i];
        float4 sv = *(const float4*)&dsm[OFF_S + i * SS + tj_ * 4];
        float l[4], mx = -INFINITY;
        l[0] = sv.x + sci + addj[0];
        l[1] = sv.y + sci + addj[1];
        l[2] = sv.z + sci + addj[2];
        l[3] = sv.w + sci + addj[3];
#pragma unroll
        for (int e = 0; e < 4; e++) mx = fmaxf(mx, l[e]);
#pragma unroll
        for (int s = 1; s < 16; s <<= 1)
            mx = fmaxf(mx, __shfl_xor_sync(0xffffffffu, mx, s));
        float num = 0.f, den = 0.f;
#pragma unroll
        for (int e = 0; e < 4; e++) {
            float ev = __expf(l[e] - mx);
            num += ev * myq1[e];
            den += ev;
        }
#pragma unroll
        for (int s = 1; s < 16; s <<= 1) {
            num += __shfl_xor_sync(0xffffffffu, num, s);
            den += __shfl_xor_sync(0xffffffffu, den, s);
        }
        if (tj_ == 0) { s_m[i] = mx; s_u[i] = num / den; }
    }
    __syncthreads();   // s_m/s_u/s_c1 ready — LAST block-wide barrier

    // ---- warp 0 runs the whole epilogue; warps 1-7 retire now ----
    if (tid >= 32) return;

    {
        float m_i = s_m[tid], c1_i = s_c1[tid];
        float mloc = m_i;
#pragma unroll
        for (int s = 16; s > 0; s >>= 1)
            mloc = fmaxf(mloc, __shfl_xor_sync(0xffffffffu, mloc, s));
        float e = __expf(m_i - mloc);
        float p = e, u = e * c1_i;
#pragma unroll
        for (int s = 16; s > 0; s >>= 1) {
            p += __shfl_xor_sync(0xffffffffu, p, s);
            u += __shfl_xor_sync(0xffffffffu, u, s);
        }
        if (tid == 0) {
            *(float4*)&g_part[(b * 16 + blockIdx.x) * 4] = make_float4(mloc, p, u, 0.f);
            __threadfence();                 // release partial
            atomicAdd(&g_cnt[b], 1u);
        }
        // every lane acquire-polls: each lane's own acquire orders its g_part read
        unsigned v;
        do {
            asm volatile("ld.global.acquire.gpu.u32 %0, [%1];"
                         : "=r"(v) : "l"(&g_cnt[b]) : "memory");
        } while (v < 16u);

        // lanes 0-15 reduce the 16 triples; H broadcast by shuffle
        float H;
        {
            int src = tid & 15;
            float4 tp = __ldcg((const float4*)&g_part[(b * 16 + src) * 4]);
            float M = tp.x;
#pragma unroll
            for (int s = 8; s > 0; s >>= 1)
                M = fmaxf(M, __shfl_xor_sync(0xffffffffu, M, s));
            float scl = __expf(tp.x - M);
            float den = tp.y * scl, num = tp.z * scl;
#pragma unroll
            for (int s = 8; s > 0; s >>= 1) {
                den += __shfl_xor_sync(0xffffffffu, den, s);
                num += __shfl_xor_sync(0xffffffffu, num, s);
            }
            H = num / den;   // lanes 0-15 and 16-31 compute identical values
        }

        // one coalesced 512B output burst for this block's 32 rows
        float U = s_u[tid], c1f = s_c1[tid];
        ((float4*)out)[(size_t)b * LC + i0 + tid] = make_float4(c1f, U, c1f * U, U * H);

        // replay-safe counter reset
        if (tid == 0) {
            unsigned old = atomicAdd(&g_cnt2[b], 1u);
            if (old == 15u) { g_cnt[b] = 0; g_cnt2[b] = 0; }
        }
    }
}

extern "C" void kernel_launch(void* const* d_in, const int* in_sizes, int n_in,
                              void* d_out, int out_size)
{
    const float* ctx   = (const float*)d_in[0];  // (8,512,256)
    const float* qst   = (const float*)d_in[1];  // (8,64,256)
    const int*   mask  = (const int*)d_in[2];    // (8,64)
    const float* att_w = (const float*)d_in[3];  // (768,)
    const float* att_b = (const float*)d_in[4];  // (1,)
    const float* w_in  = (const float*)d_in[5];  // (256,)
    const float* w_mem = (const float*)d_in[6];  // (256,)
    float* out = (float*)d_out;                  // (8,512,4)

    cudaFuncSetAttribute(bi_attn_fused,
                         cudaFuncAttributeMaxDynamicSharedMemorySize, DYN_BYTES);
    dim3 grid(LC / TI, BB);
    bi_attn_fused<<<grid, NT, DYN_BYTES>>>(ctx, qst, mask, att_w, att_b,
                                           w_in, w_mem, out);
}